// round 16
// baseline (speedup 1.0000x reference)
#include <cuda_runtime.h>
#include <cuda_bf16.h>
#include <math.h>
#include <cstdint>

// Problem constants
#define B 4
#define C 128
#define NSP 4096          // H*W*D
#define G 32
#define CPG 4             // C / G
#define DH 128

// Scratch (allocation-free rule: __device__ globals)
__device__ float2 g_stat[B * G];                 // per (b,g): mean, rstd
__device__ __nv_bfloat16 g_qh[B * NSP * C];      // (b,n,c), pre-scaled by c^-0.5*log2(e)
__device__ __nv_bfloat16 g_kh[B * NSP * C];      // (b,n,c)
__device__ __nv_bfloat16 g_vt[B * C * NSP];      // (b,c,n)  transposed V
__device__ uint32_t g_wqh[3 * 128 * 64];         // qkv_w bf16x2, [o][c/2]
__device__ uint32_t g_woh[128 * 64];             // out_w bf16x2, [o][c/2]

// ---------------------------------------------------------------------------
// helpers
// ---------------------------------------------------------------------------
__device__ __forceinline__ uint32_t smem_u32(const void* p) {
    uint32_t a;
    asm("{ .reg .u64 t; cvta.to.shared.u64 t, %1; cvt.u32.u64 %0, t; }"
        : "=r"(a) : "l"(p));
    return a;
}
__device__ __forceinline__ void ldsm4(uint32_t& r0, uint32_t& r1, uint32_t& r2,
                                      uint32_t& r3, uint32_t addr) {
    asm volatile("ldmatrix.sync.aligned.m8n8.x4.shared.b16 {%0,%1,%2,%3}, [%4];"
        : "=r"(r0), "=r"(r1), "=r"(r2), "=r"(r3) : "r"(addr));
}
__device__ __forceinline__ void ldsm4t(uint32_t& r0, uint32_t& r1, uint32_t& r2,
                                       uint32_t& r3, uint32_t addr) {
    asm volatile("ldmatrix.sync.aligned.m8n8.x4.trans.shared.b16 {%0,%1,%2,%3}, [%4];"
        : "=r"(r0), "=r"(r1), "=r"(r2), "=r"(r3) : "r"(addr));
}
__device__ __forceinline__ void mma16816(float* c, const uint32_t* a,
                                         uint32_t b0, uint32_t b1) {
    asm volatile(
        "mma.sync.aligned.m16n8k16.row.col.f32.bf16.bf16.f32 "
        "{%0,%1,%2,%3}, {%4,%5,%6,%7}, {%8,%9}, {%0,%1,%2,%3};"
        : "+f"(c[0]), "+f"(c[1]), "+f"(c[2]), "+f"(c[3])
        : "r"(a[0]), "r"(a[1]), "r"(a[2]), "r"(a[3]), "r"(b0), "r"(b1));
}
__device__ __forceinline__ uint32_t packbf(float lo, float hi) {
    uint32_t r;
    asm("cvt.rn.bf16x2.f32 %0, %1, %2;" : "=r"(r) : "f"(hi), "f"(lo));
    return r;
}
__device__ __forceinline__ float ex2(float v) {
    float r;
    asm("ex2.approx.ftz.f32 %0, %1;" : "=f"(r) : "f"(v));
    return r;
}
__device__ __forceinline__ void cpasync16(uint32_t dst, const void* src) {
    asm volatile("cp.async.cg.shared.global [%0], [%1], 16;" :: "r"(dst), "l"(src));
}
#define CP_COMMIT()  asm volatile("cp.async.commit_group;" ::: "memory")
#define CP_WAIT(n)   asm volatile("cp.async.wait_group %0;" :: "n"(n) : "memory")

#define LDB 272            // smem bytes per 128-bf16 row (136 halves, conflict-free ldmatrix)
#define TILE (128 * LDB)

// ---------------------------------------------------------------------------
// Kernel 1: GroupNorm statistics (blocks 0..127) + weight bf16 conversion
// (blocks 128..131, front-batched). 1024 threads.
// ---------------------------------------------------------------------------
__global__ __launch_bounds__(1024) void gnstat_kernel(const float* __restrict__ x,
                                                      const float* __restrict__ wq,
                                                      const float* __restrict__ wo) {
    int tid = threadIdx.x;
    if (blockIdx.x >= B * G) {
        int wb = blockIdx.x - B * G;
        float2 vv[8];
        #pragma unroll
        for (int k = 0; k < 8; k++) {
            int idx = wb * 8192 + tid + k * 1024;
            vv[k] = (idx < 24576) ? ((const float2*)wq)[idx]
                                  : ((const float2*)wo)[idx - 24576];
        }
        #pragma unroll
        for (int k = 0; k < 8; k++) {
            int idx = wb * 8192 + tid + k * 1024;
            uint32_t p = packbf(vv[k].x, vv[k].y);
            if (idx < 24576) g_wqh[idx] = p;
            else             g_woh[idx - 24576] = p;
        }
        return;
    }

    __shared__ float rs[1024], rs2[1024];
    int b = blockIdx.x >> 5;
    int g = blockIdx.x & 31;
    const float4* xp = (const float4*)(x + ((size_t)b * C + g * CPG) * NSP);

    float4 v0 = xp[tid];
    float4 v1 = xp[tid + 1024];
    float4 v2 = xp[tid + 2048];
    float4 v3 = xp[tid + 3072];
    float s  = (v0.x + v0.y + v0.z + v0.w) + (v1.x + v1.y + v1.z + v1.w)
             + (v2.x + v2.y + v2.z + v2.w) + (v3.x + v3.y + v3.z + v3.w);
    float s2 = (v0.x * v0.x + v0.y * v0.y + v0.z * v0.z + v0.w * v0.w)
             + (v1.x * v1.x + v1.y * v1.y + v1.z * v1.z + v1.w * v1.w)
             + (v2.x * v2.x + v2.y * v2.y + v2.z * v2.z + v2.w * v2.w)
             + (v3.x * v3.x + v3.y * v3.y + v3.z * v3.z + v3.w * v3.w);
    rs[tid] = s; rs2[tid] = s2;
    __syncthreads();
    #pragma unroll
    for (int off = 512; off > 0; off >>= 1) {
        if (tid < off) { rs[tid] += rs[tid + off]; rs2[tid] += rs2[tid + off]; }
        __syncthreads();
    }
    if (tid == 0) {
        const float invN = 1.0f / (CPG * NSP);
        float mean = rs[0] * invN;
        float var  = rs2[0] * invN - mean * mean;
        g_stat[blockIdx.x] = make_float2(mean, rsqrtf(var + 1e-5f));
    }
}

// ---------------------------------------------------------------------------
// Kernel 2: QKV projection, HMMA bf16, GN fused, ALL 3 ROLES per CTA.
// ---------------------------------------------------------------------------
__global__ __launch_bounds__(256, 1) void qkv_kernel(const float* __restrict__ x,
                                                     const float* __restrict__ gw,
                                                     const float* __restrict__ gb,
                                                     const float* __restrict__ bias) {
    extern __shared__ char smraw[];
    uint32_t smem = smem_u32(smraw);
    const uint32_t Xs = smem;                 // [c][s] bf16, LDB rows
    const uint32_t W0 = smem + TILE;          // [o][c] bf16 (role 0, then role 2)
    const uint32_t W1 = smem + 2 * TILE;      // [o][c] bf16 (role 1)

    int tid = threadIdx.x;
    int w = tid >> 5, t = tid & 31;
    int s0 = blockIdx.x * 128;
    int b  = blockIdx.y;

    for (int i = tid; i < 128 * 32; i += 256) {
        int c = i >> 5, s4 = i & 31;
        float2 st = g_stat[b * G + (c >> 2)];
        float wch = gw[c] * st.y;
        float bch = gb[c] - st.x * wch;
        float4 v = ((const float4*)(x + ((size_t)b * C + c) * NSP + s0))[s4];
        uint2 pk;
        pk.x = packbf(v.x * wch + bch, v.y * wch + bch);
        pk.y = packbf(v.z * wch + bch, v.w * wch + bch);
        *(uint2*)(smraw + c * LDB + s4 * 8) = pk;
    }
    for (int i = tid; i < 2 * 128 * 16; i += 256) {
        int buf = i >> 11;
        int o = (i >> 4) & 127, c8 = i & 15;
        uint4 v = ((const uint4*)(g_wqh + buf * 8192))[o * 16 + c8];
        *(uint4*)(smraw + (1 + buf) * TILE + o * LDB + c8 * 16) = v;
    }
    __syncthreads();

    uint32_t afx[8][4];
    {
        uint32_t abase = Xs + (uint32_t)(((t & 7) + ((t >> 4) & 1) * 8) * LDB
                                         + (w * 16 + ((t >> 3) & 1) * 8) * 2);
        #pragma unroll
        for (int j = 0; j < 8; j++)
            ldsm4t(afx[j][0], afx[j][1], afx[j][2], afx[j][3], abase + j * (16 * LDB));
    }

    const uint32_t bqkoff = (uint32_t)(((t & 7) + ((t >> 4) << 3)) * LDB
                                       + ((t >> 3) & 1) * 16);
    const float scale = 0.1275174331f;   // 128^-0.5 * log2(e)

    #pragma unroll
    for (int role = 0; role < 2; role++) {
        uint32_t bqk = ((role == 0) ? W0 : W1) + bqkoff;
        float acc[16][4];
        #pragma unroll
        for (int n = 0; n < 16; n++) { acc[n][0] = acc[n][1] = acc[n][2] = acc[n][3] = 0.f; }

        #pragma unroll
        for (int j = 0; j < 8; j++) {
            #pragma unroll
            for (int n2 = 0; n2 < 8; n2++) {
                uint32_t f0, f1, f2, f3;
                ldsm4(f0, f1, f2, f3, bqk + n2 * (16 * LDB) + j * 32);
                mma16816(acc[2 * n2],     afx[j], f0, f1);
                mma16816(acc[2 * n2 + 1], afx[j], f2, f3);
            }
        }

        int r0 = s0 + w * 16 + (t >> 2), r1 = r0 + 8;
        __nv_bfloat16* dst = (role == 0) ? g_qh : g_kh;
        #pragma unroll
        for (int n = 0; n < 16; n++) {
            int col = n * 8 + 2 * (t & 3);
            float bv0 = bias[role * 128 + col];
            float bv1 = bias[role * 128 + col + 1];
            float v00 = acc[n][0] + bv0, v01 = acc[n][1] + bv1;
            float v10 = acc[n][2] + bv0, v11 = acc[n][3] + bv1;
            if (role == 0) { v00 *= scale; v01 *= scale; v10 *= scale; v11 *= scale; }
            *(uint32_t*)(dst + ((size_t)(b * NSP + r0) << 7) + col) = packbf(v00, v01);
            *(uint32_t*)(dst + ((size_t)(b * NSP + r1) << 7) + col) = packbf(v10, v11);
        }
    }

    // ---- role 2 (v): A = W (m=o), B = Xs^T (n=s) ----
    __syncthreads();
    for (int i = tid; i < 128 * 16; i += 256) {
        int o = i >> 4, c8 = i & 15;
        uint4 v = ((const uint4*)(g_wqh + 2 * 8192))[o * 16 + c8];
        *(uint4*)(smraw + TILE + o * LDB + c8 * 16) = v;
    }
    __syncthreads();

    {
        uint32_t afw[8][4];
        uint32_t abase = W0 + (uint32_t)((w * 16 + (t & 7) + ((t >> 3) & 1) * 8) * LDB
                                         + (t >> 4) * 16);
        #pragma unroll
        for (int j = 0; j < 8; j++)
            ldsm4(afw[j][0], afw[j][1], afw[j][2], afw[j][3], abase + j * 32);

        float acc[16][4];
        #pragma unroll
        for (int n = 0; n < 16; n++) { acc[n][0] = acc[n][1] = acc[n][2] = acc[n][3] = 0.f; }

        uint32_t bbase = Xs + (uint32_t)(((t & 7) + ((t >> 3) & 1) * 8) * LDB
                                         + (((t >> 4) & 1) * 8) * 2);
        #pragma unroll
        for (int j = 0; j < 8; j++) {
            #pragma unroll
            for (int n2 = 0; n2 < 8; n2++) {
                uint32_t f0, f1, f2, f3;
                ldsm4t(f0, f1, f2, f3, bbase + n2 * 32 + j * (16 * LDB));
                mma16816(acc[2 * n2],     afw[j], f0, f1);
                mma16816(acc[2 * n2 + 1], afw[j], f2, f3);
            }
        }

        int o0 = w * 16 + (t >> 2), o1 = o0 + 8;
        float bv0 = bias[256 + o0], bv1 = bias[256 + o1];
        #pragma unroll
        for (int n = 0; n < 16; n++) {
            int col = n * 8 + 2 * (t & 3);
            *(uint32_t*)(g_vt + ((size_t)(b * C + o0) << 12) + s0 + col) =
                packbf(acc[n][0] + bv0, acc[n][1] + bv0);
            *(uint32_t*)(g_vt + ((size_t)(b * C + o1) << 12) + s0 + col) =
                packbf(acc[n][2] + bv1, acc[n][3] + bv1);
        }
    }
}

// ---------------------------------------------------------------------------
// Kernel 3: flash attention + fused out-projection, 3-stage cp.async pipeline.
// 6 smem regions; stage s (=kt%3) uses regions {2s, 2s+1} for K/V.
// Q preloaded into region 4 (overwritten at kt=0 body, after frags are read).
// Wo loaded into region 4 at kt=30 (region 4 last read kt=29).
// Epilogue packs O into region 0 (last read kt=30).
// ONE __syncthreads per iteration; prefetch issued after the barrier.
// ---------------------------------------------------------------------------
#define SM_ATTN (6 * TILE)

__global__ __launch_bounds__(256, 1) void attn_kernel(const float* __restrict__ obias,
                                                      const float* __restrict__ x,
                                                      float* __restrict__ out) {
    extern __shared__ char smraw[];
    uint32_t smem = smem_u32(smraw);

    int tid = threadIdx.x;
    int w = tid >> 5, t = tid & 31;
    int b = blockIdx.y, q0 = blockIdx.x * 128;

    int sr = tid >> 4, sc = tid & 15;

    const char* kbase = (const char*)(g_kh + ((size_t)b * NSP << 7));
    const char* vbase = (const char*)(g_vt + ((size_t)b * C << 12));

    // prologue: Q -> region 4 (GQ), K0/V0 -> 0,1 (G0), K1/V1 -> 2,3 (G1)
    {
        const char* qsrc = (const char*)(g_qh + ((size_t)(b * NSP + q0) << 7));
        #pragma unroll
        for (int rr = 0; rr < 8; rr++) {
            int r = sr + rr * 16;
            cpasync16(smem + 4 * TILE + r * LDB + sc * 16, qsrc + r * 256 + sc * 16);
        }
    }
    CP_COMMIT();
    #pragma unroll
    for (int rr = 0; rr < 8; rr++) {
        int r = sr + rr * 16;
        cpasync16(smem + r * LDB + sc * 16, kbase + r * 256 + sc * 16);
        cpasync16(smem + TILE + r * LDB + sc * 16, vbase + (size_t)r * 8192 + sc * 16);
    }
    CP_COMMIT();
    #pragma unroll
    for (int rr = 0; rr < 8; rr++) {
        int r = sr + rr * 16;
        cpasync16(smem + 2 * TILE + r * LDB + sc * 16, kbase + 32768 + r * 256 + sc * 16);
        cpasync16(smem + 3 * TILE + r * LDB + sc * 16,
                  vbase + (size_t)r * 8192 + 256 + sc * 16);
    }
    CP_COMMIT();

    // Q fragments from region 4 (GQ drained; G0/G1 may remain outstanding)
    CP_WAIT(2);
    uint32_t qf[8][4];
    {
        uint32_t qbase = smem + 4 * TILE
                       + (uint32_t)((w * 16 + (t & 7) + ((t >> 3) & 1) * 8) * LDB
                                    + (t >> 4) * 16);
        #pragma unroll
        for (int j = 0; j < 8; j++)
            ldsm4(qf[j][0], qf[j][1], qf[j][2], qf[j][3], qbase + j * 32);
    }

    uint32_t kvoff = (uint32_t)(((t & 7) + ((t >> 4) << 3)) * LDB + ((t >> 3) & 1) * 16);

    float O[16][4];
    #pragma unroll
    for (int n = 0; n < 16; n++) { O[n][0] = O[n][1] = O[n][2] = O[n][3] = 0.f; }
    float l0r = 0.f, l1r = 0.f;

    for (int kt = 0; kt < NSP / 128; kt++) {
        // drain group kt (leave kt+1 in flight); barrier doubles as:
        //  - data-visibility for buffer kt%3
        //  - all-warps-done with buffer (kt+2)%3 == (kt-1)%3 (distance-2 reuse)
        //  - (kt==0) all warps hold Q frags before region 4 is overwritten
        if (kt + 1 < NSP / 128) { CP_WAIT(1); } else { CP_WAIT(0); }
        __syncthreads();

        // issue prefetch AFTER the barrier
        if (kt + 2 < NSP / 128) {
            int s2 = (kt + 2) % 3;
            #pragma unroll
            for (int rr = 0; rr < 8; rr++) {
                int r = sr + rr * 16;
                cpasync16(smem + (2 * s2) * TILE + r * LDB + sc * 16,
                          kbase + (size_t)(kt + 2) * 32768 + r * 256 + sc * 16);
                cpasync16(smem + (2 * s2 + 1) * TILE + r * LDB + sc * 16,
                          vbase + (size_t)r * 8192 + (size_t)(kt + 2) * 256 + sc * 16);
            }
            CP_COMMIT();
        } else if (kt == 30) {
            // Wo -> region 4 (last read at kt=29; all warps past it)
            #pragma unroll
            for (int rr = 0; rr < 8; rr++) {
                int r = sr + rr * 16;
                cpasync16(smem + 4 * TILE + r * LDB + sc * 16,
                          (const char*)g_woh + r * 256 + sc * 16);
            }
            CP_COMMIT();
        }

        int s = kt % 3;
        uint32_t kb = smem + (2 * s) * TILE + kvoff;
        uint32_t vb = smem + (2 * s + 1) * TILE + kvoff;

        float S[16][4];
        #pragma unroll
        for (int n = 0; n < 16; n++) { S[n][0] = S[n][1] = S[n][2] = S[n][3] = 0.f; }
        #pragma unroll
        for (int j = 0; j < 8; j++) {
            #pragma unroll
            for (int n2 = 0; n2 < 8; n2++) {
                uint32_t f0, f1, f2, f3;
                ldsm4(f0, f1, f2, f3, kb + n2 * (16 * LDB) + j * 32);
                mma16816(S[2 * n2],     qf[j], f0, f1);
                mma16816(S[2 * n2 + 1], qf[j], f2, f3);
            }
        }

        // no-max softmax: P = exp2(S)
        #pragma unroll
        for (int n = 0; n < 16; n++) {
            S[n][0] = ex2(S[n][0]);
            S[n][1] = ex2(S[n][1]);
            S[n][2] = ex2(S[n][2]);
            S[n][3] = ex2(S[n][3]);
            l0r += S[n][0] + S[n][1];
            l1r += S[n][2] + S[n][3];
        }

        #pragma unroll
        for (int j = 0; j < 8; j++) {
            uint32_t pa[4];
            pa[0] = packbf(S[2 * j][0],     S[2 * j][1]);
            pa[1] = packbf(S[2 * j][2],     S[2 * j][3]);
            pa[2] = packbf(S[2 * j + 1][0], S[2 * j + 1][1]);
            pa[3] = packbf(S[2 * j + 1][2], S[2 * j + 1][3]);
            uint32_t vaddr = vb + j * 32;
            #pragma unroll
            for (int d2 = 0; d2 < 8; d2++) {
                uint32_t f0, f1, f2, f3;
                ldsm4(f0, f1, f2, f3, vaddr + d2 * (16 * LDB));
                mma16816(O[2 * d2],     pa, f0, f1);
                mma16816(O[2 * d2 + 1], pa, f2, f3);
            }
        }
    }

    // final row-sum reduction
    l0r += __shfl_xor_sync(0xffffffffu, l0r, 1);
    l0r += __shfl_xor_sync(0xffffffffu, l0r, 2);
    l1r += __shfl_xor_sync(0xffffffffu, l1r, 1);
    l1r += __shfl_xor_sync(0xffffffffu, l1r, 2);

    // ---- fused out-projection epilogue ----
    // pack normalized bf16 O tile into region 0 (last read at kt=30; all warps
    // passed kt=31's barrier, so done with it; kt=31 compute touches regions 2,3 only)
    {
        float r0 = 1.0f / l0r, r1 = 1.0f / l1r;
        int g = t >> 2, tg = t & 3;
        int row0 = w * 16 + g, row1 = row0 + 8;
        #pragma unroll
        for (int n = 0; n < 16; n++) {
            int col = n * 8 + 2 * tg;
            *(uint32_t*)(smraw + row0 * LDB + col * 2) = packbf(O[n][0] * r0, O[n][1] * r0);
            *(uint32_t*)(smraw + row1 * LDB + col * 2) = packbf(O[n][2] * r1, O[n][3] * r1);
        }
    }
    CP_WAIT(0);        // Wo group complete
    __syncthreads();   // O tile fully packed by all warps

    // GEMM: A = Wo (region 4), B = O tile (region 0)
    {
        uint32_t af[8][4];
        uint32_t abase = smem + 4 * TILE
                       + (uint32_t)((w * 16 + (t & 7) + ((t >> 3) & 1) * 8) * LDB
                                    + (t >> 4) * 16);
        #pragma unroll
        for (int j = 0; j < 8; j++)
            ldsm4(af[j][0], af[j][1], af[j][2], af[j][3], abase + j * 32);

        float acc[16][4];
        #pragma unroll
        for (int n = 0; n < 16; n++) { acc[n][0] = acc[n][1] = acc[n][2] = acc[n][3] = 0.f; }

        uint32_t bbase = smem + (uint32_t)(((t & 7) + ((t >> 4) << 3)) * LDB
                                           + ((t >> 3) & 1) * 16);
        #pragma unroll
        for (int j = 0; j < 8; j++) {
            #pragma unroll
            for (int n2 = 0; n2 < 8; n2++) {
                uint32_t f0, f1, f2, f3;
                ldsm4(f0, f1, f2, f3, bbase + n2 * (16 * LDB) + j * 32);
                mma16816(acc[2 * n2],     af[j], f0, f1);
                mma16816(acc[2 * n2 + 1], af[j], f2, f3);
            }
        }

        int o0 = w * 16 + (t >> 2), o1 = o0 + 8;
        float bv0 = obias[o0], bv1 = obias[o1];
        #pragma unroll
        for (int n = 0; n < 16; n++) {
            int col = n * 8 + 2 * (t & 3);
            size_t base0 = ((size_t)(b * C + o0) << 12) + q0 + col;
            size_t base1 = ((size_t)(b * C + o1) << 12) + q0 + col;
            float2 xv0 = *(const float2*)(x + base0);
            float2 xv1 = *(const float2*)(x + base1);
            *(float2*)(out + base0) = make_float2(acc[n][0] + bv0 + xv0.x,
                                                  acc[n][1] + bv0 + xv0.y);
            *(float2*)(out + base1) = make_float2(acc[n][2] + bv1 + xv1.x,
                                                  acc[n][3] + bv1 + xv1.y);
        }
    }
}

// ---------------------------------------------------------------------------
extern "C" void kernel_launch(void* const* d_in, const int* in_sizes, int n_in,
                              void* d_out, int out_size) {
    const float* x     = (const float*)d_in[0];
    const float* gn_w  = (const float*)d_in[1];
    const float* gn_b  = (const float*)d_in[2];
    const float* qkv_w = (const float*)d_in[3];
    const float* qkv_b = (const float*)d_in[4];
    const float* out_w = (const float*)d_in[5];
    const float* out_b = (const float*)d_in[6];
    float* out = (float*)d_out;

    static bool attrs_set = false;
    const int qkv_smem = 3 * TILE;
    if (!attrs_set) {
        cudaFuncSetAttribute(qkv_kernel,  cudaFuncAttributeMaxDynamicSharedMemorySize, qkv_smem);
        cudaFuncSetAttribute(attn_kernel, cudaFuncAttributeMaxDynamicSharedMemorySize, SM_ATTN);
        attrs_set = true;
    }

    gnstat_kernel<<<B * G + 4, 1024>>>(x, qkv_w, out_w);
    qkv_kernel<<<dim3(NSP / 128, B), 256, qkv_smem>>>(x, gn_w, gn_b, qkv_b);
    attn_kernel<<<dim3(NSP / 128, B), 256, SM_ATTN>>>(out_b, x, out);
}